// round 14
// baseline (speedup 1.0000x reference)
#include <cuda_runtime.h>
#include <math.h>

// Problem constants
#define BB 16
#define CC 512
#define NN 1024   // H*W
#define GG 32
#define CG 16     // CC/GG
#define TEXT 180
#define FF 1024
#define EPSV 1e-6f
#define SCALE 0.04419417382415922f   // 512^-0.5
#define ROWS 32   // n-rows per fused attn_out block

// ---- scratch (static device memory) ----
__device__ float d_wg[CC];        // final colsum[c]*gamma[c]
__device__ float d_wosum[CC];
__device__ float d_wgsum[GG];
__device__ float d_c0part[GG];
__device__ float d_bqsum;
__device__ float d_k[BB*FF];
__device__ float d_v[BB*FF];
__device__ float d_psum[BB*GG*2];     // per-half stats partials
__device__ float d_psum2[BB*GG*2];
__device__ __align__(16) float d_P[BB*GG*NN];  // 2 MB

// ============================================================
// Kernel 0: prep — wq colsums ONLY (what gn needs)
// 16 blocks, each finalizes 32 columns (2 groups)
// ============================================================
__global__ void prep_kernel(const float* __restrict__ gamma,
                            const float* __restrict__ beta,
                            const float* __restrict__ wq)
{
    __shared__ float4 swp[8][8];
    __shared__ float gpart[8][2];

    int blk = blockIdx.x;
    int tid = threadIdx.x;
    const float4* wq4 = (const float4*)wq;
    int warp = tid >> 5, lane = tid & 31;
    int c4 = lane & 7;
    int r  = tid >> 3;

    float4 pa = make_float4(0.f, 0.f, 0.f, 0.f);
    #pragma unroll
    for (int k = 0; k < 16; k++) {
        float4 w = wq4[(r + 32 * k) * 128 + blk * 8 + c4];
        pa.x += w.x; pa.y += w.y; pa.z += w.z; pa.w += w.w;
    }
    #pragma unroll
    for (int off = 8; off <= 16; off <<= 1) {
        pa.x += __shfl_xor_sync(0xffffffffu, pa.x, off);
        pa.y += __shfl_xor_sync(0xffffffffu, pa.y, off);
        pa.z += __shfl_xor_sync(0xffffffffu, pa.z, off);
        pa.w += __shfl_xor_sync(0xffffffffu, pa.w, off);
    }
    if (lane < 8) swp[warp][c4] = pa;
    __syncthreads();

    if (tid < 8) {
        float4 cs = swp[0][tid];
        #pragma unroll
        for (int w = 1; w < 8; w++) {
            float4 t = swp[w][tid];
            cs.x += t.x; cs.y += t.y; cs.z += t.z; cs.w += t.w;
        }
        int gc4 = blk * 8 + tid;
        float4 gm = ((const float4*)gamma)[gc4];
        float4 bt = ((const float4*)beta)[gc4];
        float4 wg;
        wg.x = cs.x * gm.x; wg.y = cs.y * gm.y;
        wg.z = cs.z * gm.z; wg.w = cs.w * gm.w;
        ((float4*)d_wg)[gc4] = wg;
        gpart[tid][0] = wg.x + wg.y + wg.z + wg.w;
        gpart[tid][1] = cs.x * bt.x + cs.y * bt.y + cs.z * bt.z + cs.w * bt.w;
    }
    __syncthreads();
    if (tid < 2) {
        float ws = 0.f, cp = 0.f;
        #pragma unroll
        for (int i = 0; i < 4; i++) {
            ws += gpart[4 * tid + i][0];
            cp += gpart[4 * tid + i][1];
        }
        d_wgsum[2 * blk + tid]  = ws;
        d_c0part[2 * blk + tid] = cp;
    }
}

// ============================================================
// Kernel 1: gn streaming + independent side roles (feed attn_out only)
//   blocks 0..1023    : gn role (16 ch x 512 n each)
//   blocks 1024..1151 : k/v projection (one per (b, f-chunk, k|v))
//   blocks 1152..1159 : wo row sums
//   block  1160       : bq sum
// ============================================================
__global__ void gn_kernel(const float* __restrict__ x,
                          const float* __restrict__ cond,
                          const float* __restrict__ wk,
                          const float* __restrict__ bk,
                          const float* __restrict__ wv,
                          const float* __restrict__ bv,
                          const float* __restrict__ wo,
                          const float* __restrict__ bq)
{
    int blk = blockIdx.x;
    int tid = threadIdx.x;

    if (blk < 1024) {
        // ---------------- gn role ----------------
        __shared__ float wgs[16];
        __shared__ float4 pshare[128];
        __shared__ float sw[8], sw2[8];

        int bg = blk >> 1, h = blk & 1;
        int b = bg >> 5, g = bg & 31;
        int c0 = g * CG;
        int hi = tid >> 7, lo = tid & 127;
        int warp = tid >> 5, lane = tid & 31;

        if (tid < 16) wgs[tid] = d_wg[c0 + tid];
        __syncthreads();

        const float4* x4 = (const float4*)x + (size_t)(b * CC + c0) * 256 + h * 128;

        float4 xv[8];
        #pragma unroll
        for (int j = 0; j < 8; j++)
            xv[j] = x4[(hi + 2 * j) * 256 + lo];

        float4 pn = make_float4(0.f, 0.f, 0.f, 0.f);
        float s = 0.f, s2 = 0.f;
        #pragma unroll
        for (int j = 0; j < 8; j++) {
            float w = wgs[hi + 2 * j];
            float4 v = xv[j];
            pn.x = fmaf(w, v.x, pn.x);
            pn.y = fmaf(w, v.y, pn.y);
            pn.z = fmaf(w, v.z, pn.z);
            pn.w = fmaf(w, v.w, pn.w);
            s  += v.x + v.y + v.z + v.w;
            s2 += v.x*v.x + v.y*v.y + v.z*v.z + v.w*v.w;
        }

        if (hi == 1) pshare[lo] = pn;

        #pragma unroll
        for (int off = 16; off > 0; off >>= 1) {
            s  += __shfl_xor_sync(0xffffffffu, s,  off);
            s2 += __shfl_xor_sync(0xffffffffu, s2, off);
        }
        if (lane == 0) { sw[warp] = s; sw2[warp] = s2; }
        __syncthreads();

        if (hi == 0) {
            float4 t = pshare[lo];
            pn.x += t.x; pn.y += t.y; pn.z += t.z; pn.w += t.w;
            ((float4*)d_P)[bg * 256 + h * 128 + lo] = pn;
        }
        if (tid == 0) {
            float ts = 0.f, ts2 = 0.f;
            #pragma unroll
            for (int i = 0; i < 8; i++) { ts += sw[i]; ts2 += sw2[i]; }
            d_psum[blk]  = ts;
            d_psum2[blk] = ts2;
        }
    } else if (blk < 1024 + 128) {
        // ---------------- k/v projection: one per (b, chunk, k|v) ----------------
        __shared__ float cs[TEXT];
        int blk2  = blk - 1024;
        int b     = blk2 >> 3;
        int chunk = (blk2 >> 1) & 3;
        int isv   = blk2 & 1;
        int f = (chunk << 8) + tid;
        if (tid < TEXT) cs[tid] = cond[b * TEXT + tid];
        __syncthreads();

        const float* wrow  = isv ? wv : wk;
        const float* brow  = isv ? bv : bk;
        float acc = brow[f];
        const float4* wr = (const float4*)(wrow + (size_t)f * TEXT);
        const float4* cs4 = (const float4*)cs;
        #pragma unroll 9
        for (int t = 0; t < TEXT / 4; t++) {
            float4 c = cs4[t];
            float4 w = wr[t];
            acc = fmaf(c.x, w.x, acc); acc = fmaf(c.y, w.y, acc);
            acc = fmaf(c.z, w.z, acc); acc = fmaf(c.w, w.w, acc);
        }
        if (isv) d_v[b * FF + f] = acc;
        else     d_k[b * FF + f] = acc;
    } else if (blk < 1024 + 128 + 8) {
        // ---------------- wo row sums ----------------
        int blk3 = blk - (1024 + 128);
        int warp = tid >> 5, lane = tid & 31;
        int o = blk3 * 64 + warp * 8;
        #pragma unroll
        for (int j = 0; j < 8; j++) {
            const float4* wr = (const float4*)(wo + (size_t)(o + j) * CC);
            float s = 0.f;
            #pragma unroll
            for (int c = 0; c < 4; c++) {
                float4 v = wr[lane + c * 32];
                s += v.x + v.y + v.z + v.w;
            }
            #pragma unroll
            for (int off = 16; off > 0; off >>= 1)
                s += __shfl_down_sync(0xffffffffu, s, off);
            if (lane == 0) d_wosum[o + j] = s;
        }
    } else {
        if (tid < 32) {
            float s = 0.f;
            #pragma unroll
            for (int i = 0; i < CC / 32; i++) s += bq[tid + i * 32];
            #pragma unroll
            for (int off = 16; off > 0; off >>= 1)
                s += __shfl_down_sync(0xffffffffu, s, off);
            if (tid == 0) d_bqsum = s;
        }
    }
}

// ============================================================
// Kernel 2 (fused): attn (32 n-rows, h2 in smem) + out streaming
// grid 512 (= B * NN/32), block 256
// ============================================================
__global__ void attn_out_kernel(const float* __restrict__ x,
                                const float* __restrict__ bo,
                                float* __restrict__ y)
{
    int blk = blockIdx.x;
    int b  = blk >> 5;
    int t  = blk & 31;
    int n0 = t * ROWS;
    int tid = threadIdx.x;
    int warp = tid >> 5, lane = tid & 31;

    __shared__ float ks[FF], vs[FF];
    __shared__ float wos[CC], bos[CC];
    __shared__ float Ps[GG][ROWS + 1];
    __shared__ float Ss[ROWS];
    __shared__ __align__(16) float h2s[ROWS];
    __shared__ float rstd_s[GG];
    __shared__ float red[20];

    // ---- phase 1: attn ----
    for (int i = tid; i < FF; i += 256) {
        ks[i] = d_k[b * FF + i];
        vs[i] = d_v[b * FF + i];
    }
    for (int i = tid; i < CC; i += 256) {
        wos[i] = d_wosum[i];
        bos[i] = bo[i];
    }
    for (int i = tid; i < GG * ROWS; i += 256) {
        int g = i >> 5, nn = i & (ROWS - 1);
        Ps[g][nn] = d_P[(size_t)(b * GG + g) * NN + n0 + nn];
    }
    float mu_l = 0.f;
    if (tid < GG) {
        int base = (b * GG + tid) * 2;
        float ps  = d_psum [base] + d_psum [base + 1];
        float ps2 = d_psum2[base] + d_psum2[base + 1];
        float mean = ps * (1.f / 16384.f);
        float var  = ps2 * (1.f / 16384.f) - mean * mean;
        rstd_s[tid] = rsqrtf(var + EPSV);
        mu_l = mean;
    }
    __syncthreads();

    float km = -1e30f, kn = 1e30f;
    for (int i = tid; i < FF; i += 256) {
        float kk = ks[i];
        km = fmaxf(km, kk);
        kn = fminf(kn, kk);
    }
    #pragma unroll
    for (int off = 16; off > 0; off >>= 1) {
        km = fmaxf(km, __shfl_xor_sync(0xffffffffu, km, off));
        kn = fminf(kn, __shfl_xor_sync(0xffffffffu, kn, off));
    }
    if (lane == 0) { red[warp] = km; red[8 + warp] = kn; }
    float Tp = 0.f;
    if (tid < GG)
        Tp = -mu_l * rstd_s[tid] * d_wgsum[tid] + d_c0part[tid];
    if (warp == 0) {
        #pragma unroll
        for (int off = 16; off > 0; off >>= 1)
            Tp += __shfl_xor_sync(0xffffffffu, Tp, off);
        if (lane == 0) red[16] = Tp + d_bqsum;
    }
    __syncthreads();

    float kmax = red[0], kmin = red[8];
    #pragma unroll
    for (int i = 1; i < 8; i++) {
        kmax = fmaxf(kmax, red[i]);
        kmin = fminf(kmin, red[8 + i]);
    }
    float Tc = red[16];

    if (tid < ROWS) {
        float s = Tc;
        #pragma unroll
        for (int g = 0; g < GG; g++) s = fmaf(rstd_s[g], Ps[g][tid], s);
        Ss[tid] = SCALE * s;
    }
    __syncthreads();

    for (int r = warp; r < ROWS; r += 8) {
        float a = Ss[r];
        float shift = (a >= 0.f) ? a * kmax : a * kmin;
        float num = 0.f, den = 0.f;
        #pragma unroll
        for (int f = lane; f < FF; f += 32) {
            float e = __expf(fmaf(a, ks[f], -shift));
            den += e;
            num = fmaf(vs[f], e, num);
        }
        #pragma unroll
        for (int off = 16; off > 0; off >>= 1) {
            num += __shfl_xor_sync(0xffffffffu, num, off);
            den += __shfl_xor_sync(0xffffffffu, den, off);
        }
        if (lane == 0) h2s[r] = num / den;
    }
    __syncthreads();

    // ---- phase 2: stream y[b, :, n0:n0+32] ----
    int n4   = tid & 7;          // which float4 of 8 in the 32-float row
    int orow = tid >> 3;         // 0..31

    float4 h2v = ((const float4*)h2s)[n4];

    const float4* xb = (const float4*)x + (size_t)b * CC * 256 + t * 8 + n4;
    float4*       yb = (float4*)y       + (size_t)b * CC * 256 + t * 8 + n4;

    #pragma unroll 1
    for (int it = 0; it < 16; it += 4) {
        float4 xv[4];
        #pragma unroll
        for (int j = 0; j < 4; j++) {
            int o = orow + (it + j) * 32;
            xv[j] = xb[(size_t)o * 256];
        }
        #pragma unroll
        for (int j = 0; j < 4; j++) {
            int o = orow + (it + j) * 32;
            float ws = wos[o];
            float bb = bos[o];
            float4 r;
            r.x = fmaf(h2v.x, ws, xv[j].x + bb);
            r.y = fmaf(h2v.y, ws, xv[j].y + bb);
            r.z = fmaf(h2v.z, ws, xv[j].z + bb);
            r.w = fmaf(h2v.w, ws, xv[j].w + bb);
            yb[(size_t)o * 256] = r;
        }
    }
}

// ============================================================
extern "C" void kernel_launch(void* const* d_in, const int* in_sizes, int n_in,
                              void* d_out, int out_size)
{
    const float* x     = (const float*)d_in[0];
    const float* cond  = (const float*)d_in[1];
    const float* gamma = (const float*)d_in[2];
    const float* beta  = (const float*)d_in[3];
    const float* wq    = (const float*)d_in[4];
    const float* bq    = (const float*)d_in[5];
    const float* wk    = (const float*)d_in[6];
    const float* bk    = (const float*)d_in[7];
    const float* wv    = (const float*)d_in[8];
    const float* bv    = (const float*)d_in[9];
    const float* wo    = (const float*)d_in[10];
    const float* bo    = (const float*)d_in[11];
    float* y = (float*)d_out;

    prep_kernel<<<16, 256>>>(gamma, beta, wq);
    gn_kernel<<<1024 + 128 + 8 + 1, 256>>>(x, cond, wk, bk, wv, bv, wo, bq);
    attn_out_kernel<<<BB * (NN / ROWS), 256>>>(x, bo, y);
}

// round 15
// speedup vs baseline: 1.1861x; 1.1861x over previous
#include <cuda_runtime.h>
#include <math.h>

// Problem constants
#define BB 16
#define CC 512
#define NN 1024   // H*W
#define GG 32
#define CG 16     // CC/GG
#define TEXT 180
#define FF 1024
#define EPSV 1e-6f
#define SCALE 0.04419417382415922f   // 512^-0.5
#define ROWS 32   // n-rows per fused attn_out block

// ---- scratch (static device memory) ----
__device__ float d_wg[CC];        // final colsum[c]*gamma[c]
__device__ float d_gw4[128];      // per-float4-col sum of wg (wgsum partials)
__device__ float d_gc4[128];      // per-float4-col colsum·beta (c0 partials)
__device__ float d_wosum[CC];
__device__ float d_bqsum;
__device__ float d_k[BB*FF];
__device__ float d_v[BB*FF];
__device__ float d_psum[BB*GG*2];     // per-half stats partials
__device__ float d_psum2[BB*GG*2];
__device__ __align__(16) float d_P[BB*GG*NN];  // 2 MB

// ============================================================
// Kernel 0: prep — all roles sized for the LSU/latency floor
//   blocks 0..127   : wq colsum, ONE float4-column each
//   blocks 128..255 : k/v projection, one per (b, f-chunk, k|v)
//   blocks 256..263 : wo row sums
//   block  264      : bq sum
// ============================================================
__global__ void prep_kernel(const float* __restrict__ cond,
                            const float* __restrict__ gamma,
                            const float* __restrict__ beta,
                            const float* __restrict__ wq,
                            const float* __restrict__ bq,
                            const float* __restrict__ wk,
                            const float* __restrict__ bk,
                            const float* __restrict__ wv,
                            const float* __restrict__ bv,
                            const float* __restrict__ wo)
{
    int blk = blockIdx.x;
    int tid = threadIdx.x;
    int warp = tid >> 5, lane = tid & 31;

    if (blk < 128) {
        // ---- colsum for float4-column blk over all 512 rows ----
        __shared__ float4 swp[8];
        const float4* wq4 = (const float4*)wq;
        float4 a = wq4[(size_t)tid * 128 + blk];
        float4 b = wq4[(size_t)(tid + 256) * 128 + blk];
        float4 pa;
        pa.x = a.x + b.x; pa.y = a.y + b.y;
        pa.z = a.z + b.z; pa.w = a.w + b.w;
        #pragma unroll
        for (int off = 16; off > 0; off >>= 1) {
            pa.x += __shfl_xor_sync(0xffffffffu, pa.x, off);
            pa.y += __shfl_xor_sync(0xffffffffu, pa.y, off);
            pa.z += __shfl_xor_sync(0xffffffffu, pa.z, off);
            pa.w += __shfl_xor_sync(0xffffffffu, pa.w, off);
        }
        if (lane == 0) swp[warp] = pa;
        __syncthreads();
        if (tid == 0) {
            float4 cs = swp[0];
            #pragma unroll
            for (int w = 1; w < 8; w++) {
                float4 t = swp[w];
                cs.x += t.x; cs.y += t.y; cs.z += t.z; cs.w += t.w;
            }
            float4 gm = ((const float4*)gamma)[blk];
            float4 bt = ((const float4*)beta)[blk];
            float4 wg;
            wg.x = cs.x * gm.x; wg.y = cs.y * gm.y;
            wg.z = cs.z * gm.z; wg.w = cs.w * gm.w;
            ((float4*)d_wg)[blk] = wg;
            d_gw4[blk] = wg.x + wg.y + wg.z + wg.w;
            d_gc4[blk] = cs.x * bt.x + cs.y * bt.y + cs.z * bt.z + cs.w * bt.w;
        }
    } else if (blk < 256) {
        // ---- k/v projection: one per (b, chunk, k|v) ----
        __shared__ float cs[TEXT];
        int blk2  = blk - 128;
        int b     = blk2 >> 3;
        int chunk = (blk2 >> 1) & 3;
        int isv   = blk2 & 1;
        int f = (chunk << 8) + tid;
        if (tid < TEXT) cs[tid] = cond[b * TEXT + tid];
        __syncthreads();

        const float* wrow = isv ? wv : wk;
        const float* brow = isv ? bv : bk;
        float acc = brow[f];
        const float4* wr  = (const float4*)(wrow + (size_t)f * TEXT);
        const float4* cs4 = (const float4*)cs;
        #pragma unroll 9
        for (int t = 0; t < TEXT / 4; t++) {
            float4 c = cs4[t];
            float4 w = wr[t];
            acc = fmaf(c.x, w.x, acc); acc = fmaf(c.y, w.y, acc);
            acc = fmaf(c.z, w.z, acc); acc = fmaf(c.w, w.w, acc);
        }
        if (isv) d_v[b * FF + f] = acc;
        else     d_k[b * FF + f] = acc;
    } else if (blk < 264) {
        // ---- wo row sums ----
        int blk3 = blk - 256;
        int o = blk3 * 64 + warp * 8;
        #pragma unroll
        for (int j = 0; j < 8; j++) {
            const float4* wr = (const float4*)(wo + (size_t)(o + j) * CC);
            float s = 0.f;
            #pragma unroll
            for (int c = 0; c < 4; c++) {
                float4 v = wr[lane + c * 32];
                s += v.x + v.y + v.z + v.w;
            }
            #pragma unroll
            for (int off = 16; off > 0; off >>= 1)
                s += __shfl_down_sync(0xffffffffu, s, off);
            if (lane == 0) d_wosum[o + j] = s;
        }
    } else {
        if (tid < 32) {
            float s = 0.f;
            #pragma unroll
            for (int i = 0; i < CC / 32; i++) s += bq[tid + i * 32];
            #pragma unroll
            for (int off = 16; off > 0; off >>= 1)
                s += __shfl_down_sync(0xffffffffu, s, off);
            if (tid == 0) d_bqsum = s;
        }
    }
}

// ============================================================
// Kernel 1: gn — pure streaming pass over x (R12's measured-good form)
// grid 1024 (= B*G*2), block = (bg, half of n): 16 ch x 512 n (32KB)
// ============================================================
__global__ void gn_kernel(const float* __restrict__ x)
{
    __shared__ float wgs[16];
    __shared__ float4 pshare[128];
    __shared__ float sw[8], sw2[8];

    int blk = blockIdx.x;
    int tid = threadIdx.x;
    int bg = blk >> 1, h = blk & 1;
    int b = bg >> 5, g = bg & 31;
    int c0 = g * CG;
    int hi = tid >> 7, lo = tid & 127;
    int warp = tid >> 5, lane = tid & 31;

    if (tid < 16) wgs[tid] = d_wg[c0 + tid];
    __syncthreads();

    const float4* x4 = (const float4*)x + (size_t)(b * CC + c0) * 256 + h * 128;

    float4 xv[8];
    #pragma unroll
    for (int j = 0; j < 8; j++)
        xv[j] = x4[(hi + 2 * j) * 256 + lo];

    float4 pn = make_float4(0.f, 0.f, 0.f, 0.f);
    float s = 0.f, s2 = 0.f;
    #pragma unroll
    for (int j = 0; j < 8; j++) {
        float w = wgs[hi + 2 * j];
        float4 v = xv[j];
        pn.x = fmaf(w, v.x, pn.x);
        pn.y = fmaf(w, v.y, pn.y);
        pn.z = fmaf(w, v.z, pn.z);
        pn.w = fmaf(w, v.w, pn.w);
        s  += v.x + v.y + v.z + v.w;
        s2 += v.x*v.x + v.y*v.y + v.z*v.z + v.w*v.w;
    }

    if (hi == 1) pshare[lo] = pn;

    #pragma unroll
    for (int off = 16; off > 0; off >>= 1) {
        s  += __shfl_xor_sync(0xffffffffu, s,  off);
        s2 += __shfl_xor_sync(0xffffffffu, s2, off);
    }
    if (lane == 0) { sw[warp] = s; sw2[warp] = s2; }
    __syncthreads();

    if (hi == 0) {
        float4 t = pshare[lo];
        pn.x += t.x; pn.y += t.y; pn.z += t.z; pn.w += t.w;
        ((float4*)d_P)[bg * 256 + h * 128 + lo] = pn;
    }
    if (tid == 0) {
        float ts = 0.f, ts2 = 0.f;
        #pragma unroll
        for (int i = 0; i < 8; i++) { ts += sw[i]; ts2 += sw2[i]; }
        d_psum[blk]  = ts;
        d_psum2[blk] = ts2;
    }
}

// ============================================================
// Kernel 2 (fused): attn (32 n-rows, h2 in smem) + out streaming
// grid 512 (= B * NN/32), block 256
// ============================================================
__global__ void attn_out_kernel(const float* __restrict__ x,
                                const float* __restrict__ bo,
                                float* __restrict__ y)
{
    int blk = blockIdx.x;
    int b  = blk >> 5;
    int t  = blk & 31;
    int n0 = t * ROWS;
    int tid = threadIdx.x;
    int warp = tid >> 5, lane = tid & 31;

    __shared__ float ks[FF], vs[FF];
    __shared__ float wos[CC], bos[CC];
    __shared__ float Ps[GG][ROWS + 1];
    __shared__ float Ss[ROWS];
    __shared__ __align__(16) float h2s[ROWS];
    __shared__ float rstd_s[GG];
    __shared__ float red[20];

    // ---- phase 1: attn ----
    for (int i = tid; i < FF; i += 256) {
        ks[i] = d_k[b * FF + i];
        vs[i] = d_v[b * FF + i];
    }
    for (int i = tid; i < CC; i += 256) {
        wos[i] = d_wosum[i];
        bos[i] = bo[i];
    }
    for (int i = tid; i < GG * ROWS; i += 256) {
        int g = i >> 5, nn = i & (ROWS - 1);
        Ps[g][nn] = d_P[(size_t)(b * GG + g) * NN + n0 + nn];
    }
    float mu_l = 0.f, wgsum_l = 0.f, c0_l = 0.f;
    if (tid < GG) {
        int base = (b * GG + tid) * 2;
        float ps  = d_psum [base] + d_psum [base + 1];
        float ps2 = d_psum2[base] + d_psum2[base + 1];
        float mean = ps * (1.f / 16384.f);
        float var  = ps2 * (1.f / 16384.f) - mean * mean;
        rstd_s[tid] = rsqrtf(var + EPSV);
        mu_l = mean;
        int q = tid * 4;
        wgsum_l = (d_gw4[q] + d_gw4[q + 1]) + (d_gw4[q + 2] + d_gw4[q + 3]);
        c0_l    = (d_gc4[q] + d_gc4[q + 1]) + (d_gc4[q + 2] + d_gc4[q + 3]);
    }
    __syncthreads();

    float km = -1e30f, kn = 1e30f;
    for (int i = tid; i < FF; i += 256) {
        float kk = ks[i];
        km = fmaxf(km, kk);
        kn = fminf(kn, kk);
    }
    #pragma unroll
    for (int off = 16; off > 0; off >>= 1) {
        km = fmaxf(km, __shfl_xor_sync(0xffffffffu, km, off));
        kn = fminf(kn, __shfl_xor_sync(0xffffffffu, kn, off));
    }
    if (lane == 0) { red[warp] = km; red[8 + warp] = kn; }
    float Tp = 0.f;
    if (tid < GG)
        Tp = -mu_l * rstd_s[tid] * wgsum_l + c0_l;
    if (warp == 0) {
        #pragma unroll
        for (int off = 16; off > 0; off >>= 1)
            Tp += __shfl_xor_sync(0xffffffffu, Tp, off);
        if (lane == 0) red[16] = Tp + d_bqsum;
    }
    __syncthreads();

    float kmax = red[0], kmin = red[8];
    #pragma unroll
    for (int i = 1; i < 8; i++) {
        kmax = fmaxf(kmax, red[i]);
        kmin = fminf(kmin, red[8 + i]);
    }
    float Tc = red[16];

    if (tid < ROWS) {
        float s = Tc;
        #pragma unroll
        for (int g = 0; g < GG; g++) s = fmaf(rstd_s[g], Ps[g][tid], s);
        Ss[tid] = SCALE * s;
    }
    __syncthreads();

    for (int r = warp; r < ROWS; r += 8) {
        float a = Ss[r];
        float shift = (a >= 0.f) ? a * kmax : a * kmin;
        float num = 0.f, den = 0.f;
        #pragma unroll
        for (int f = lane; f < FF; f += 32) {
            float e = __expf(fmaf(a, ks[f], -shift));
            den += e;
            num = fmaf(vs[f], e, num);
        }
        #pragma unroll
        for (int off = 16; off > 0; off >>= 1) {
            num += __shfl_xor_sync(0xffffffffu, num, off);
            den += __shfl_xor_sync(0xffffffffu, den, off);
        }
        if (lane == 0) h2s[r] = num / den;
    }
    __syncthreads();

    // ---- phase 2: stream y[b, :, n0:n0+32] ----
    int n4   = tid & 7;          // which float4 of 8 in the 32-float row
    int orow = tid >> 3;         // 0..31

    float4 h2v = ((const float4*)h2s)[n4];

    const float4* xb = (const float4*)x + (size_t)b * CC * 256 + t * 8 + n4;
    float4*       yb = (float4*)y       + (size_t)b * CC * 256 + t * 8 + n4;

    #pragma unroll 1
    for (int it = 0; it < 16; it += 4) {
        float4 xv[4];
        #pragma unroll
        for (int j = 0; j < 4; j++) {
            int o = orow + (it + j) * 32;
            xv[j] = xb[(size_t)o * 256];
        }
        #pragma unroll
        for (int j = 0; j < 4; j++) {
            int o = orow + (it + j) * 32;
            float ws = wos[o];
            float bb = bos[o];
            float4 r;
            r.x = fmaf(h2v.x, ws, xv[j].x + bb);
            r.y = fmaf(h2v.y, ws, xv[j].y + bb);
            r.z = fmaf(h2v.z, ws, xv[j].z + bb);
            r.w = fmaf(h2v.w, ws, xv[j].w + bb);
            yb[(size_t)o * 256] = r;
        }
    }
}

// ============================================================
extern "C" void kernel_launch(void* const* d_in, const int* in_sizes, int n_in,
                              void* d_out, int out_size)
{
    const float* x     = (const float*)d_in[0];
    const float* cond  = (const float*)d_in[1];
    const float* gamma = (const float*)d_in[2];
    const float* beta  = (const float*)d_in[3];
    const float* wq    = (const float*)d_in[4];
    const float* bq    = (const float*)d_in[5];
    const float* wk    = (const float*)d_in[6];
    const float* bk    = (const float*)d_in[7];
    const float* wv    = (const float*)d_in[8];
    const float* bv    = (const float*)d_in[9];
    const float* wo    = (const float*)d_in[10];
    const float* bo    = (const float*)d_in[11];
    float* y = (float*)d_out;

    prep_kernel<<<265, 256>>>(cond, gamma, beta, wq, bq, wk, bk, wv, bv, wo);
    gn_kernel<<<BB * GG * 2, 256>>>(x);
    attn_out_kernel<<<BB * (NN / ROWS), 256>>>(x, bo, y);
}